// round 8
// baseline (speedup 1.0000x reference)
#include <cuda_runtime.h>
#include <cstdint>

#define NQ   32
#define KCB  1024
#define CD   8
#define DD   1024
#define TT   4096
#define BB   8
#define NCOL (BB * TT)

#define QOUT_ELEMS (BB * DD * TT)
#define IDX_ELEMS  (NQ * BB * TT)
#define FULL_OUT   (QOUT_ELEMS + IDX_ELEMS + BB)

typedef unsigned long long u64t;

__device__ __forceinline__ u64t pk2(float a, float b) {
    u64t r; asm("mov.b64 %0,{%1,%2};" : "=l"(r) : "f"(a), "f"(b)); return r;
}
__device__ __forceinline__ float2 upk2(u64t v) {
    float2 r; asm("mov.b64 {%0,%1},%2;" : "=f"(r.x), "=f"(r.y) : "l"(v)); return r;
}
__device__ __forceinline__ void fma2(u64t& d, u64t a, u64t b) {
    asm("fma.rn.f32x2 %0,%1,%2,%0;" : "+l"(d) : "l"(a), "l"(b));
}
__device__ __forceinline__ u64t mul2(u64t a, u64t b) {
    u64t r; asm("mul.rn.f32x2 %0,%1,%2;" : "=l"(r) : "l"(a), "l"(b)); return r;
}

// scratch (device globals; zero-alloc rule)
__device__ float g_ZE0[256 * NCOL];      // 32 MB   [mc][col]
__device__ float g_ZQ [256 * NCOL];      // 32 MB   [mc][col], masked zq
__device__ float g_G  [256 * 256];       // Gmat[mci][ncj]
__device__ float g_WoT[DD * 256];        // [d][mc]
__device__ float g_cbn[NQ * KCB * CD];
__device__ float g_wboT[NQ * NQ * CD];   // wbo[m][n][c]
__device__ float g_wboCum[NQ * CD];
__device__ float g_bsum[DD];
__device__ int   g_len[BB];

// ---------------- kPre: transposes, cbn, bsum, wboT, len ----------------
__global__ void kPre(const float* __restrict__ W_in, const float* __restrict__ b_in,
                     const float* __restrict__ W_out, const float* __restrict__ b_out,
                     const float* __restrict__ cb, const long long* __restrict__ len64,
                     float* __restrict__ out, int out_size) {
    int tid = blockIdx.x * blockDim.x + threadIdx.x;   // 0..262143
    { // WoT[d][mc] = W_out[mc>>3][d][mc&7]
        int d = tid >> 8, mc = tid & 255;
        g_WoT[d * 256 + mc] = W_out[((size_t)(mc >> 3) * DD + d) * CD + (mc & 7)];
    }
    if (tid < NQ * KCB) { // normalized codebooks
        const float* row = cb + (size_t)tid * CD;
        float v[8], n2 = 0.0f;
#pragma unroll
        for (int i = 0; i < 8; i++) { v[i] = row[i]; n2 = fmaf(v[i], v[i], n2); }
        float s = fmaxf(__fsqrt_rn(n2), 1e-12f);
#pragma unroll
        for (int i = 0; i < 8; i++) g_cbn[(size_t)tid * CD + i] = __fdiv_rn(v[i], s);
    }
    if (tid < NQ * NQ * CD) { // wbo[m][n][c] = W_in^m[c]·b_out^n
        int m = tid >> 8, n = (tid >> 3) & 31, c = tid & 7;
        const float* wr = W_in + ((size_t)m * CD + c) * DD;
        const float* br = b_out + (size_t)n * DD;
        float acc = 0.0f;
        for (int d = 0; d < DD; d++) acc = fmaf(wr[d], br[d], acc);
        g_wboT[tid] = acc;
    }
    if (tid < DD) { // bsum
        float s = 0.0f;
        for (int n = 0; n < NQ; n++) s += b_out[(size_t)n * DD + tid];
        g_bsum[tid] = s;
    }
    if (tid == 0) {
        long long tmp[BB]; bool ok = true;
        for (int i = 0; i < BB; i++) { tmp[i] = len64[i]; if (tmp[i] < 0 || tmp[i] > TT) ok = false; }
        if (ok) for (int i = 0; i < BB; i++) g_len[i] = (int)tmp[i];
        else { const int* l = (const int*)len64; for (int i = 0; i < BB; i++) g_len[i] = l[i]; }
        if (out_size >= FULL_OUT)
            for (int i = 0; i < BB; i++) out[QOUT_ELEMS + IDX_ELEMS + i] = (float)g_len[i];
    }
}

// ---------------- kG: Gmat = Win_all x WoT; wboCum ----------------
__global__ void kG(const float* __restrict__ W_in) {
    int tid = blockIdx.x * blockDim.x + threadIdx.x;   // 65536
    int row = tid >> 8, col = tid & 255;
    const float* a = W_in + (size_t)row * DD;          // Win row mc (row-major)
    float acc = 0.0f;
    for (int d = 0; d < DD; d++) acc = fmaf(a[d], g_WoT[d * 256 + col], acc);
    g_G[row * 256 + col] = acc;
    if (tid < NQ * CD) {
        int m = tid >> 3, c = tid & 7;
        float s = 0.0f;
        for (int n = 0; n < m; n++) s += g_wboT[(m * 32 + n) * 8 + c];
        g_wboCum[tid] = s;
    }
}

// ---------------- gemmZE: ZE0 = mask * (Win_all x z) ----------------
__global__ void __launch_bounds__(256)
gemmZE(const float* __restrict__ A, const float* __restrict__ z) {
    __shared__ float As[16 * 64];
    __shared__ float Bs[16 * 136];
    const int tid = threadIdx.x;
    const int bm  = blockIdx.x * 64;
    const int cb0 = blockIdx.y * 128;
    const int b   = cb0 >> 12, t0 = cb0 & 4095;
    const int len = g_len[b];
    const int tx = tid & 15, ty = tid >> 4;
    const float* zb = z + (size_t)b * DD * TT + t0;

    u64t acc[4][4];
#pragma unroll
    for (int i = 0; i < 4; i++)
#pragma unroll
        for (int p = 0; p < 4; p++) acc[i][p] = 0ull;

    for (int kk = 0; kk < 1024; kk += 16) {
        {
            float4 av = *reinterpret_cast<const float4*>(
                A + (size_t)(bm + (tid & 63)) * DD + kk + (tid >> 6) * 4);
            int kb = (tid >> 6) * 4, m = tid & 63;
            As[(kb + 0) * 64 + m] = av.x; As[(kb + 1) * 64 + m] = av.y;
            As[(kb + 2) * 64 + m] = av.z; As[(kb + 3) * 64 + m] = av.w;
#pragma unroll
            for (int it = 0; it < 2; it++) {
                int f = it * 256 + tid, row = f >> 5, c4 = f & 31;
                *reinterpret_cast<float4*>(&Bs[row * 136 + c4 * 4]) =
                    *reinterpret_cast<const float4*>(zb + (size_t)(kk + row) * TT + c4 * 4);
            }
        }
        __syncthreads();
#pragma unroll
        for (int k = 0; k < 16; k++) {
            float4 a4 = *reinterpret_cast<const float4*>(&As[k * 64 + ty * 4]);
            ulonglong2 b0 = *reinterpret_cast<const ulonglong2*>(&Bs[k * 136 + tx * 8]);
            ulonglong2 b1 = *reinterpret_cast<const ulonglong2*>(&Bs[k * 136 + tx * 8 + 4]);
            float aa[4] = {a4.x, a4.y, a4.z, a4.w};
#pragma unroll
            for (int i = 0; i < 4; i++) {
                u64t ap = pk2(aa[i], aa[i]);
                fma2(acc[i][0], ap, b0.x); fma2(acc[i][1], ap, b0.y);
                fma2(acc[i][2], ap, b1.x); fma2(acc[i][3], ap, b1.y);
            }
        }
        __syncthreads();
    }
#pragma unroll
    for (int i = 0; i < 4; i++) {
        int row = bm + ty * 4 + i;
        float* dst = g_ZE0 + (size_t)row * NCOL + cb0 + tx * 8;
#pragma unroll
        for (int p = 0; p < 4; p++) {
            float2 u = upk2(acc[i][p]);
            int tt = t0 + tx * 8 + 2 * p;
            u.x *= (tt < len) ? 1.0f : 0.0f;
            u.y *= (tt + 1 < len) ? 1.0f : 0.0f;
            *reinterpret_cast<float2*>(dst + 2 * p) = u;
        }
    }
}

// ---------------- rvq_scan: sequential quantization ----------------
__global__ void __launch_bounds__(128)
rvq_scan(const float* __restrict__ b_in, const float* __restrict__ cb,
         float* __restrict__ out, int out_size) {
    __shared__ float sCbn[KCB * CD];     // 32 KB
    __shared__ float sG[64 * 64];        // 16 KB
    const int tid = threadIdx.x;
    const int col = blockIdx.x * 128 + tid;
    const int b = col >> 12, t = col & 4095;
    const float mask = (t < g_len[b]) ? 1.0f : 0.0f;
    const bool write_idx = (out_size >= QOUT_ELEMS + IDX_ELEMS);

    u64t zqh[32];    // chunk history: [jj*4+p], masked zq pairs

    for (int c = 0; c < 4; c++) {
        // stage in-chunk G block (rows c*64, cols c*64)
        __syncthreads();
#pragma unroll
        for (int it = 0; it < 8; it++) {
            int f = it * 128 + tid, ri = f >> 4, kq = f & 15;
            *reinterpret_cast<float4*>(&sG[ri * 64 + kq * 4]) =
                *reinterpret_cast<const float4*>(&g_G[(c * 64 + ri) * 256 + c * 64 + kq * 4]);
        }
        __syncthreads();

#pragma unroll
        for (int j = 0; j < 8; j++) {
            const int nq = c * 8 + j;
            // stage codebook for this step
            __syncthreads();
#pragma unroll
            for (int it = 0; it < 16; it++) {
                int f = it * 128 + tid;
                *reinterpret_cast<float4*>(&sCbn[f * 4]) =
                    *reinterpret_cast<const float4*>(&g_cbn[(size_t)nq * 8192 + f * 4]);
            }
            __syncthreads();

            // build ze
            float e[8];
#pragma unroll
            for (int cc = 0; cc < 8; cc++)
                e[cc] = g_ZE0[(size_t)(nq * 8 + cc) * NCOL + col]
                      + __ldg(b_in + nq * 8 + cc)
                      - mask * __ldg(g_wboCum + nq * 8 + cc);
#pragma unroll
            for (int jj = 0; jj < 8; jj++) {
                if (jj >= j) break;
#pragma unroll
                for (int ci = 0; ci < 8; ci++) {
                    const u64t* gp = reinterpret_cast<const u64t*>(
                        &sG[(j * 8 + ci) * 64 + jj * 8]);
                    u64t a = mul2(gp[0], zqh[jj * 4 + 0]);
                    fma2(a, gp[1], zqh[jj * 4 + 1]);
                    fma2(a, gp[2], zqh[jj * 4 + 2]);
                    fma2(a, gp[3], zqh[jj * 4 + 3]);
                    float2 u = upk2(a);
                    e[ci] -= (u.x + u.y);
                }
            }
            u64t zep[4];
#pragma unroll
            for (int p = 0; p < 4; p++) zep[p] = pk2(e[2 * p], e[2 * p + 1]);

            // argmax over K
            float best = -3.4e38f; int bk = 0;
            const ulonglong2* cb2 = reinterpret_cast<const ulonglong2*>(sCbn);
#pragma unroll 4
            for (int k = 0; k < KCB; k++) {
                ulonglong2 cA = cb2[k * 2], cB = cb2[k * 2 + 1];
                u64t dp = mul2(zep[0], cA.x);
                fma2(dp, zep[1], cA.y);
                fma2(dp, zep[2], cB.x);
                fma2(dp, zep[3], cB.y);
                float2 u = upk2(dp);
                float d = u.x + u.y;
                if (d > best) { best = d; bk = k; }
            }

            // gather raw codeword, mask, record
            {
                const ulonglong2* pcb = reinterpret_cast<const ulonglong2*>(
                    cb + ((size_t)nq * KCB + bk) * CD);
                ulonglong2 qa = __ldg(pcb), qb = __ldg(pcb + 1);
                u64t mm = pk2(mask, mask);
                zqh[j * 4 + 0] = mul2(qa.x, mm);
                zqh[j * 4 + 1] = mul2(qa.y, mm);
                zqh[j * 4 + 2] = mul2(qb.x, mm);
                zqh[j * 4 + 3] = mul2(qb.y, mm);
#pragma unroll
                for (int p = 0; p < 4; p++) {
                    float2 u = upk2(zqh[j * 4 + p]);
                    g_ZQ[(size_t)(nq * 8 + 2 * p) * NCOL + col] = u.x;
                    g_ZQ[(size_t)(nq * 8 + 2 * p + 1) * NCOL + col] = u.y;
                }
                if (write_idx)
                    out[QOUT_ELEMS + (size_t)(nq * BB + b) * TT + t] = (float)bk;
            }
        }

        // fold chunk contribution into future ZE0 rows
        for (int fc = c + 1; fc < 4; fc++) {
            __syncthreads();
#pragma unroll
            for (int it = 0; it < 8; it++) {
                int f = it * 128 + tid, ri = f >> 4, kq = f & 15;
                *reinterpret_cast<float4*>(&sG[ri * 64 + kq * 4]) =
                    *reinterpret_cast<const float4*>(&g_G[(fc * 64 + ri) * 256 + c * 64 + kq * 4]);
            }
            __syncthreads();
#pragma unroll 2
            for (int r = 0; r < 64; r++) {
                const u64t* gp = reinterpret_cast<const u64t*>(&sG[r * 64]);
                u64t a = mul2(gp[0], zqh[0]);
#pragma unroll
                for (int q = 1; q < 32; q++) fma2(a, gp[q], zqh[q]);
                float2 u = upk2(a);
                size_t idx = (size_t)(fc * 64 + r) * NCOL + col;
                g_ZE0[idx] -= (u.x + u.y);
            }
        }
    }
}

// ---------------- gemmQ: qout = WoT x ZQ + mask*bsum ----------------
__global__ void __launch_bounds__(256)
gemmQ(float* __restrict__ out, int out_size) {
    __shared__ float As[16 * 64];
    __shared__ float Bs[16 * 136];
    if (out_size < QOUT_ELEMS) return;
    const int tid = threadIdx.x;
    const int bm  = blockIdx.x * 64;
    const int cb0 = blockIdx.y * 128;
    const int b   = cb0 >> 12, t0 = cb0 & 4095;
    const int len = g_len[b];
    const int tx = tid & 15, ty = tid >> 4;

    u64t acc[4][4];
#pragma unroll
    for (int i = 0; i < 4; i++)
#pragma unroll
        for (int p = 0; p < 4; p++) acc[i][p] = 0ull;

    for (int kk = 0; kk < 256; kk += 16) {
        {
            float4 av = *reinterpret_cast<const float4*>(
                g_WoT + (size_t)(bm + (tid & 63)) * 256 + kk + (tid >> 6) * 4);
            int kb = (tid >> 6) * 4, m = tid & 63;
            As[(kb + 0) * 64 + m] = av.x; As[(kb + 1) * 64 + m] = av.y;
            As[(kb + 2) * 64 + m] = av.z; As[(kb + 3) * 64 + m] = av.w;
#pragma unroll
            for (int it = 0; it < 2; it++) {
                int f = it * 256 + tid, row = f >> 5, c4 = f & 31;
                *reinterpret_cast<float4*>(&Bs[row * 136 + c4 * 4]) =
                    *reinterpret_cast<const float4*>(g_ZQ + (size_t)(kk + row) * NCOL + cb0 + c4 * 4);
            }
        }
        __syncthreads();
#pragma unroll
        for (int k = 0; k < 16; k++) {
            float4 a4 = *reinterpret_cast<const float4*>(&As[k * 64 + ty * 4]);
            ulonglong2 b0 = *reinterpret_cast<const ulonglong2*>(&Bs[k * 136 + tx * 8]);
            ulonglong2 b1 = *reinterpret_cast<const ulonglong2*>(&Bs[k * 136 + tx * 8 + 4]);
            float aa[4] = {a4.x, a4.y, a4.z, a4.w};
#pragma unroll
            for (int i = 0; i < 4; i++) {
                u64t ap = pk2(aa[i], aa[i]);
                fma2(acc[i][0], ap, b0.x); fma2(acc[i][1], ap, b0.y);
                fma2(acc[i][2], ap, b1.x); fma2(acc[i][3], ap, b1.y);
            }
        }
        __syncthreads();
    }
#pragma unroll
    for (int i = 0; i < 4; i++) {
        int d = bm + ty * 4 + i;
        float bs = __ldg(g_bsum + d);
        float* dst = out + (size_t)b * DD * TT + (size_t)d * TT + t0 + tx * 8;
#pragma unroll
        for (int p = 0; p < 4; p++) {
            float2 u = upk2(acc[i][p]);
            int tt = t0 + tx * 8 + 2 * p;
            float m0 = (tt < len) ? 1.0f : 0.0f;
            float m1 = (tt + 1 < len) ? 1.0f : 0.0f;
            u.x += m0 * bs;  u.y += m1 * bs;
            u.x *= m0;       u.y *= m1;      // masked cols -> 0 (ZQ cols already 0)
            *reinterpret_cast<float2*>(dst + 2 * p) = u;
        }
    }
}

// ---------------------------------------------------------------------------
extern "C" void kernel_launch(void* const* d_in, const int* in_sizes, int n_in,
                              void* d_out, int out_size) {
    const float*     z     = (const float*)d_in[0];
    const long long* len   = (const long long*)d_in[1];
    const float*     W_in  = (const float*)d_in[2];
    const float*     b_in  = (const float*)d_in[3];
    const float*     W_out = (const float*)d_in[4];
    const float*     b_out = (const float*)d_in[5];
    const float*     cbk   = (const float*)d_in[6];
    float* out = (float*)d_out;

    kPre<<<1024, 256>>>(W_in, b_in, W_out, b_out, cbk, len, out, out_size);
    kG<<<256, 256>>>(W_in);
    gemmZE<<<dim3(4, 256), 256>>>(W_in, z);
    rvq_scan<<<256, 128>>>(b_in, cbk, out, out_size);
    gemmQ<<<dim3(16, 256), 256>>>(out, out_size);
}